// round 4
// baseline (speedup 1.0000x reference)
#include <cuda_runtime.h>
#include <cstdint>

#define N_PTS 8192
#define DIM 64
#define BM 128
#define NT (N_PTS / BM)            // 64 tiles per side
#define NPAIR (NT * (NT + 1) / 2)  // 2080 tile pairs
#define NTHREADS 256

// Scratch (no allocation). All writes are idempotent pure functions of the
// inputs — no atomics, no zero-then-accumulate — replay/overlap safe.
__device__ float g_sq[N_PTS];
__device__ float g_ru[N_PTS];            // 1/(1-||x||^2)
__device__ int   g_lab[N_PTS];
__device__ float g_pse[NT * N_PTS];      // partial sum exp(-d), slot = other tile idx
__device__ float g_psl[NT * N_PTS];      // partial sum log r over positives
__device__ int   g_pct[NT * N_PTS];      // partial positive counts
__device__ float g_rowloss[N_PTS];

__global__ void prep_kernel(const float* __restrict__ pts,
                            const long long* __restrict__ labs) {
    int i = blockIdx.x * blockDim.x + threadIdx.x;
    if (i >= N_PTS) return;
    const float4* p = (const float4*)(pts + i * DIM);
    float s = 0.f;
#pragma unroll
    for (int q = 0; q < DIM / 4; q++) {
        float4 v = p[q];
        s += v.x * v.x + v.y * v.y + v.z * v.z + v.w * v.w;
    }
    g_sq[i] = s;
    g_ru[i] = 1.0f / (1.0f - s);
    g_lab[i] = (int)labs[i];
}

__device__ __forceinline__ float fast_sqrt(float x) {
    float r; asm("sqrt.approx.f32 %0, %1;" : "=f"(r) : "f"(x)); return r;
}
__device__ __forceinline__ float fast_rcp(float x) {
    float r; asm("rcp.approx.f32 %0, %1;" : "=f"(r) : "f"(x)); return r;
}

__global__ __launch_bounds__(NTHREADS, 2)
void main_kernel(const float* __restrict__ pts) {
    __shared__ float As[DIM * BM];   // 32KB  [k][m], resident whole block
    __shared__ float Bs[32 * BM];    // 16KB  [kk][n], two k-halves
    const float4* P4 = (const float4*)pts;
    int tid = threadIdx.x;
    int tx = tid & 15, ty = tid >> 4;

    // Decode linear block -> upper-triangular tile pair (ti <= tj).
    int b = blockIdx.x;
    int ti = (int)floorf((129.0f - sqrtf(16641.0f - 8.0f * (float)b)) * 0.5f);
    if (ti < 0) ti = 0;
    if (ti > NT - 1) ti = NT - 1;
    while (ti > 0 && b < ti * (129 - ti) / 2) ti--;
    while (b >= (ti + 1) * (128 - ti) / 2) ti++;
    int tj = ti + (b - ti * (129 - ti) / 2);
    bool isdiag = (ti == tj);
    int i0 = ti * BM, j0 = tj * BM;

    // Load A tile transposed [k][m]
#pragma unroll
    for (int it = 0; it < (BM * DIM / 4) / NTHREADS; it++) {
        int idx = tid + it * NTHREADS;
        int m = idx & (BM - 1);
        int q = idx >> 7;
        float4 v = P4[(i0 + m) * (DIM / 4) + q];
        As[(4 * q + 0) * BM + m] = v.x;
        As[(4 * q + 1) * BM + m] = v.y;
        As[(4 * q + 2) * BM + m] = v.z;
        As[(4 * q + 3) * BM + m] = v.w;
    }

    float acc[8][8];
#pragma unroll
    for (int r = 0; r < 8; r++)
#pragma unroll
        for (int c = 0; c < 8; c++) acc[r][c] = 0.f;

#pragma unroll
    for (int kh = 0; kh < 2; kh++) {
        __syncthreads();
#pragma unroll
        for (int it = 0; it < (BM * 32 / 4) / NTHREADS; it++) {
            int idx = tid + it * NTHREADS;
            int n = idx & (BM - 1);
            int q = idx >> 7;
            float4 v = P4[(j0 + n) * (DIM / 4) + kh * 8 + q];
            Bs[(4 * q + 0) * BM + n] = v.x;
            Bs[(4 * q + 1) * BM + n] = v.y;
            Bs[(4 * q + 2) * BM + n] = v.z;
            Bs[(4 * q + 3) * BM + n] = v.w;
        }
        __syncthreads();
#pragma unroll
        for (int kk = 0; kk < 32; kk++) {
            int k = kh * 32 + kk;
            float4 a0 = *(const float4*)&As[k * BM + ty * 4];
            float4 a1 = *(const float4*)&As[k * BM + 64 + ty * 4];
            float4 b0 = *(const float4*)&Bs[kk * BM + tx * 4];
            float4 b1 = *(const float4*)&Bs[kk * BM + 64 + tx * 4];
            float a[8] = {a0.x, a0.y, a0.z, a0.w, a1.x, a1.y, a1.z, a1.w};
            float bb[8] = {b0.x, b0.y, b0.z, b0.w, b1.x, b1.y, b1.z, b1.w};
#pragma unroll
            for (int r = 0; r < 8; r++)
#pragma unroll
                for (int c = 0; c < 8; c++)
                    acc[r][c] = fmaf(a[r], bb[c], acc[r][c]);
        }
    }

    // ---- Pass 1: convert acc in place to rv = exp(-d) = 1/(z + sqrt(z^2-1)),
    //      with diagonal elements masked to exactly 0 (real rv >= ~3e-3).
    int labj[8], labi[8];
    float sqj[8], ruj[8];
#pragma unroll
    for (int c = 0; c < 8; c++) {
        int col = ((c & 4) << 4) + tx * 4 + (c & 3);
        int g = j0 + col;
        sqj[c] = g_sq[g]; ruj[c] = g_ru[g]; labj[c] = g_lab[g];
    }
#pragma unroll
    for (int r = 0; r < 8; r++) {
        int row = ((r & 4) << 4) + ty * 4 + (r & 3);
        int gi = i0 + row;
        float sqi  = g_sq[gi];
        float rui2 = 2.0f * g_ru[gi];
        labi[r] = g_lab[gi];
        int colbase = j0 + ((0 & 4) << 4); (void)colbase;
#pragma unroll
        for (int c = 0; c < 8; c++) {
            int col = ((c & 4) << 4) + tx * 4 + (c & 3);
            int gj = j0 + col;
            float sqd = fmaxf(fmaf(-2.0f, acc[r][c], sqi + sqj[c]), 0.f);
            float z = fmaf(sqd * rui2, ruj[c], 1.0f);
            z = fmaxf(z, 1.0f + 1e-7f);
            float t = fmaf(z, z, -1.0f);
            float s = fast_sqrt(t);
            float rv = fast_rcp(z + s);
            acc[r][c] = (gi != gj) ? rv : 0.f;
        }
    }

    // ---- Pass 2 (row side): per r, reduce over c then over tx.
#pragma unroll
    for (int r = 0; r < 8; r++) {
        float se = 0.f, pr = 1.f;
        int ct = 0;
#pragma unroll
        for (int c = 0; c < 8; c++) {
            float v = acc[r][c];
            bool pos = (labi[r] == labj[c]) && (v != 0.f);
            se += v;
            pr *= pos ? v : 1.f;
            ct += pos;
        }
        float sl = __log2f(pr) * 0.69314718055994531f;
#pragma unroll
        for (int s = 8; s > 0; s >>= 1) {
            se += __shfl_xor_sync(0xffffffffu, se, s);
            sl += __shfl_xor_sync(0xffffffffu, sl, s);
            ct += __shfl_xor_sync(0xffffffffu, ct, s);
        }
        if (tx == 0) {
            int row = ((r & 4) << 4) + ty * 4 + (r & 3);
            int slot = tj * N_PTS + (i0 + row);
            g_pse[slot] = se;
            g_psl[slot] = sl;
            g_pct[slot] = ct;
        }
    }

    // ---- Pass 3 (col side): per c, reduce over r then over ty (via smem).
    if (!isdiag) {
        __syncthreads();                 // As dead after GEMM; reuse as scratch
        float* sse = As;                 // [8 c][8 warps][16 tx]
        float* ssl = As + 1024;
        int*   sct = (int*)(As + 2048);
        int w = tid >> 5;
        bool lo = (tid & 31) < 16;
#pragma unroll
        for (int c = 0; c < 8; c++) {
            float se = 0.f, pr = 1.f;
            int ct = 0;
#pragma unroll
            for (int r = 0; r < 8; r++) {
                float v = acc[r][c];
                bool pos = (labi[r] == labj[c]) && (v != 0.f);
                se += v;
                pr *= pos ? v : 1.f;
                ct += pos;
            }
            float sl = __log2f(pr) * 0.69314718055994531f;
            se += __shfl_xor_sync(0xffffffffu, se, 16);
            sl += __shfl_xor_sync(0xffffffffu, sl, 16);
            ct += __shfl_xor_sync(0xffffffffu, ct, 16);
            if (lo) {
                int o = c * 128 + w * 16 + tx;
                sse[o] = se; ssl[o] = sl; sct[o] = ct;
            }
        }
        __syncthreads();
        if (tid < 128) {
            int txq = tid >> 3, cq = tid & 7;
            float se = 0.f, sl = 0.f; int ct = 0;
#pragma unroll
            for (int ww = 0; ww < 8; ww++) {
                int o = cq * 128 + ww * 16 + txq;
                se += sse[o]; sl += ssl[o]; ct += sct[o];
            }
            int col = ((cq & 4) << 4) + txq * 4 + (cq & 3);
            int slot = ti * N_PTS + (j0 + col);
            g_pse[slot] = se;
            g_psl[slot] = sl;
            g_pct[slot] = ct;
        }
    }
}

// Fold the 64 tile-slot partials per row (fixed-order, deterministic).
__global__ void rowred_kernel() {
    int i = blockIdx.x * blockDim.x + threadIdx.x;
    if (i >= N_PTS) return;
    float se = 0.f, sl = 0.f;
    int ct = 0;
#pragma unroll 8
    for (int t = 0; t < NT; t++) {
        se += g_pse[t * N_PTS + i];
        sl += g_psl[t * N_PTS + i];
        ct += g_pct[t * N_PTS + i];
    }
    float logA = __logf(fmaxf(se, 1e-30f));
    float P = (float)(ct > 0 ? ct : 1);
    g_rowloss[i] = logA - sl / P;
}

__global__ void final_kernel(float* __restrict__ out) {
    __shared__ float red[256];
    int t = threadIdx.x;
    float acc = 0.f;
#pragma unroll
    for (int it = 0; it < N_PTS / 256; it++)
        acc += g_rowloss[t + it * 256];
    red[t] = acc;
    __syncthreads();
    for (int s = 128; s > 0; s >>= 1) {
        if (t < s) red[t] += red[t + s];
        __syncthreads();
    }
    if (t == 0) out[0] = red[0];
}

extern "C" void kernel_launch(void* const* d_in, const int* in_sizes, int n_in,
                              void* d_out, int out_size) {
    const float* pts = (const float*)d_in[0];
    const long long* labs = (const long long*)d_in[1];
    prep_kernel<<<N_PTS / 256, 256>>>(pts, labs);
    main_kernel<<<NPAIR, NTHREADS>>>(pts);
    rowred_kernel<<<N_PTS / 256, 256>>>();
    final_kernel<<<1, 256>>>((float*)d_out);
}

// round 6
// speedup vs baseline: 1.1491x; 1.1491x over previous
#include <cuda_runtime.h>
#include <cuda_bf16.h>
#include <cstdint>

#define N_PTS 8192
#define DIM 64
#define BM 128
#define NT (N_PTS / BM)            // 64 tiles per side
#define NPAIR (NT * (NT + 1) / 2)  // 2080 tile pairs
#define NTHREADS 256
#define TILE_B 16384               // 128 rows x 64 bf16 (128B rows)

// ---- scratch (device globals; all writes idempotent, replay-safe) ----
__device__ __align__(16) __nv_bfloat16 g_xhi[N_PTS * DIM];
__device__ __align__(16) __nv_bfloat16 g_xlo[N_PTS * DIM];
__device__ float g_sq[N_PTS];
__device__ float g_ru[N_PTS];
__device__ int   g_lab[N_PTS];
__device__ float g_pse[2 * NT * N_PTS];
__device__ float g_psl[2 * NT * N_PTS];
__device__ int   g_pct[2 * NT * N_PTS];
__device__ float g_rowloss[N_PTS];

__device__ __forceinline__ uint32_t smem_u32(const void* p) {
    uint32_t a;
    asm("{ .reg .u64 t; cvta.to.shared.u64 t, %1; cvt.u32.u64 %0, t; }" : "=r"(a) : "l"(p));
    return a;
}
__device__ __forceinline__ float fast_sqrt(float x) {
    float r; asm("sqrt.approx.f32 %0, %1;" : "=f"(r) : "f"(x)); return r;
}
__device__ __forceinline__ float fast_rcp(float x) {
    float r; asm("rcp.approx.f32 %0, %1;" : "=f"(r) : "f"(x)); return r;
}
__device__ __forceinline__ void ldsm4(uint32_t* r, uint32_t addr) {
    asm volatile("ldmatrix.sync.aligned.m8n8.x4.shared.b16 {%0,%1,%2,%3}, [%4];"
                 : "=r"(r[0]), "=r"(r[1]), "=r"(r[2]), "=r"(r[3]) : "r"(addr));
}
__device__ __forceinline__ void mma_bf16(float* d, const uint32_t* a,
                                         uint32_t b0, uint32_t b1) {
    asm("mma.sync.aligned.m16n8k16.row.col.f32.bf16.bf16.f32 "
        "{%0,%1,%2,%3}, {%4,%5,%6,%7}, {%8,%9}, {%0,%1,%2,%3};"
        : "+f"(d[0]), "+f"(d[1]), "+f"(d[2]), "+f"(d[3])
        : "r"(a[0]), "r"(a[1]), "r"(a[2]), "r"(a[3]), "r"(b0), "r"(b1));
}

// ---- prep: bf16 2-term split + per-point metadata ----
__global__ void prep_kernel(const float* __restrict__ pts,
                            const long long* __restrict__ labs) {
    int i = blockIdx.x * blockDim.x + threadIdx.x;
    if (i >= N_PTS) return;
    float s = 0.f;
#pragma unroll
    for (int q = 0; q < DIM; q++) {
        float x = pts[i * DIM + q];
        s = fmaf(x, x, s);
        __nv_bfloat16 hi = __float2bfloat16(x);
        __nv_bfloat16 lo = __float2bfloat16(x - __bfloat162float(hi));
        g_xhi[i * DIM + q] = hi;
        g_xlo[i * DIM + q] = lo;
    }
    g_sq[i] = s;
    g_ru[i] = 1.0f / (1.0f - s);
    g_lab[i] = (int)labs[i];
}

// ---- main: HMMA tile-pair kernel, dual-side epilogue ----
__global__ __launch_bounds__(NTHREADS, 1)
void main_kernel() {
    extern __shared__ __align__(16) char dsm_raw[];
    __shared__ float2 s_mi[BM], s_mj[BM];
    __shared__ int s_li[BM], s_lj[BM];

    uint32_t dsm0 = smem_u32(dsm_raw);
    uint32_t dsm = (dsm0 + 127u) & ~127u;          // 128B align (bank-pattern period)
    char* dsmp = dsm_raw + (dsm - dsm0);

    int tid = threadIdx.x;
    int w = tid >> 5, lane = tid & 31;
    int mr = (w & 3) * 32;                          // warp row base (4 row-warps)
    int nc = (w >> 2) * 64;                         // warp col base (2 col-warps)
    int t8 = lane >> 3, rs = lane & 7;              // ldmatrix tile id / row-in-tile

    // decode linear block -> upper-triangular pair (ti <= tj)
    int b = blockIdx.x;
    int ti = (int)floorf((129.0f - sqrtf(16641.0f - 8.0f * (float)b)) * 0.5f);
    if (ti < 0) ti = 0;
    if (ti > NT - 1) ti = NT - 1;
    while (ti > 0 && b < ti * (129 - ti) / 2) ti--;
    while (b >= (ti + 1) * (128 - ti) / 2) ti++;
    int tj = ti + (b - ti * (129 - ti) / 2);
    bool isdiag = (ti == tj);
    int i0 = ti * BM, j0 = tj * BM;

    // ---- load 4 tiles (Ahi,Alo,Bhi,Blo) with XOR-chunk swizzle ----
    const uint4* HI = (const uint4*)g_xhi;          // 8 uint4 per point
    const uint4* LO = (const uint4*)g_xlo;
#pragma unroll
    for (int it = 0; it < 16; it++) {
        int idx = tid + it * NTHREADS;              // 0..4095
        int tile = idx >> 10;                       // 0:Ah 1:Al 2:Bh 3:Bl
        int cidx = idx & 1023;
        int row = cidx >> 3, q = cidx & 7;
        int base = (tile & 2) ? j0 : i0;
        const uint4* src = (tile & 1) ? LO : HI;
        uint4 v = src[(base + row) * 8 + q];
        uint32_t off = (uint32_t)(row * 128) + (uint32_t)((q ^ (row & 7)) << 4);
        *(uint4*)(dsmp + tile * TILE_B + off) = v;
    }
    if (tid < BM) {
        int g = j0 + tid;
        s_mj[tid] = make_float2(g_sq[g], g_ru[g]);
        s_lj[tid] = g_lab[g];
    } else {
        int r = tid - BM, g = i0 + r;
        s_mi[r] = make_float2(g_sq[g], g_ru[g]);
        s_li[r] = g_lab[g];
    }
    __syncthreads();

    // ---- 3-term split GEMM via HMMA ----
    float d[2][8][4];
#pragma unroll
    for (int mf = 0; mf < 2; mf++)
#pragma unroll
        for (int nb = 0; nb < 8; nb++)
#pragma unroll
            for (int k = 0; k < 4; k++) d[mf][nb][k] = 0.f;

#pragma unroll
    for (int ks = 0; ks < 4; ks++) {
        uint32_t ah[2][4], al[2][4];
#pragma unroll
        for (int mf = 0; mf < 2; mf++) {
            int rowA = mr + mf * 16 + (t8 & 1) * 8 + rs;
            int ch = ks * 2 + (t8 >> 1);
            uint32_t sw = (uint32_t)(rowA * 128) + (uint32_t)((ch ^ (rowA & 7)) << 4);
            ldsm4(ah[mf], dsm + 0 * TILE_B + sw);
            ldsm4(al[mf], dsm + 1 * TILE_B + sw);
        }
#pragma unroll
        for (int nbp = 0; nbp < 4; nbp++) {
            int rowB = nc + nbp * 16 + (t8 >> 1) * 8 + rs;
            int ch = ks * 2 + (t8 & 1);
            uint32_t sw = (uint32_t)(rowB * 128) + (uint32_t)((ch ^ (rowB & 7)) << 4);
            uint32_t bh[4], bl[4];
            ldsm4(bh, dsm + 2 * TILE_B + sw);
            ldsm4(bl, dsm + 3 * TILE_B + sw);
#pragma unroll
            for (int mf = 0; mf < 2; mf++)
#pragma unroll
                for (int nbi = 0; nbi < 2; nbi++) {
                    float* dd = d[mf][nbp * 2 + nbi];
                    mma_bf16(dd, ah[mf], bh[2 * nbi], bh[2 * nbi + 1]);
                    mma_bf16(dd, ah[mf], bl[2 * nbi], bl[2 * nbi + 1]);
                    mma_bf16(dd, al[mf], bh[2 * nbi], bh[2 * nbi + 1]);
                }
        }
    }

    // ---- epilogue: rv = exp(-d) = 1/(z+sqrt(z^2-1)); dual-side accumulate ----
    float sqr[4], rur[4];
    int labr[4], grow[4];
#pragma unroll
    for (int f = 0; f < 4; f++) {                   // f = mf*2 + hi
        int rloc = mr + (f >> 1) * 16 + (f & 1) * 8 + (lane >> 2);
        grow[f] = i0 + rloc;
        float2 m = s_mi[rloc];
        sqr[f] = m.x; rur[f] = 2.0f * m.y; labr[f] = s_li[rloc];
    }
    float rse[4], rpr[4];
    int rea[4], rct[4];
#pragma unroll
    for (int f = 0; f < 4; f++) { rse[f] = 0.f; rpr[f] = 1.f; rea[f] = 0; rct[f] = 0; }

    // col-partial staging buffers (reuse tile smem after sync below)
    float* st_se = (float*)dsmp;                    // [128 col][32 idx]
    float* st_sl = (float*)(dsmp + 16384);
    int*   st_ct = (int*)(dsmp + 32768);
    int cidx = (w & 3) * 8 + (lane >> 2);           // which 32-row group

    float csl_buf[8][2]; float cse_buf[8][2]; int cct_buf[8][2];

#pragma unroll
    for (int nb = 0; nb < 8; nb++) {
        int c0 = nc + nb * 8 + (lane & 3) * 2;
        float2 mj0 = s_mj[c0], mj1 = s_mj[c0 + 1];
        int lj0 = s_lj[c0], lj1 = s_lj[c0 + 1];
        int gc0 = j0 + c0, gc1 = gc0 + 1;
        float cse0 = 0.f, cse1 = 0.f, cpr0 = 1.f, cpr1 = 1.f;
        int cct0 = 0, cct1 = 0;
#pragma unroll
        for (int f = 0; f < 4; f++) {
            float dot0 = d[f >> 1][nb][(f & 1) * 2 + 0];
            float dot1 = d[f >> 1][nb][(f & 1) * 2 + 1];
            // element 0
            {
                float sqd = fmaxf(fmaf(-2.0f, dot0, sqr[f] + mj0.x), 0.f);
                float z = fmaf(sqd * rur[f], mj0.y, 1.0f);
                z = fmaxf(z, 1.0f + 1e-7f);
                float s = fast_sqrt(fmaf(z, z, -1.0f));
                float rv = fast_rcp(z + s);
                bool offd = (grow[f] != gc0);
                bool pos = offd && (labr[f] == lj0);
                float rve = offd ? rv : 0.f;
                float rvp = pos ? rv : 1.f;
                rse[f] += rve; rpr[f] *= rvp; rct[f] += pos;
                cse0 += rve; cpr0 *= rvp; cct0 += pos;
            }
            // element 1
            {
                float sqd = fmaxf(fmaf(-2.0f, dot1, sqr[f] + mj1.x), 0.f);
                float z = fmaf(sqd * rur[f], mj1.y, 1.0f);
                z = fmaxf(z, 1.0f + 1e-7f);
                float s = fast_sqrt(fmaf(z, z, -1.0f));
                float rv = fast_rcp(z + s);
                bool offd = (grow[f] != gc1);
                bool pos = offd && (labr[f] == lj1);
                float rve = offd ? rv : 0.f;
                float rvp = pos ? rv : 1.f;
                rse[f] += rve; rpr[f] *= rvp; rct[f] += pos;
                cse1 += rve; cpr1 *= rvp; cct1 += pos;
            }
        }
        cse_buf[nb][0] = cse0; cse_buf[nb][1] = cse1;
        csl_buf[nb][0] = __log2f(cpr0);             // <=4 factors, no underflow
        csl_buf[nb][1] = __log2f(cpr1);
        cct_buf[nb][0] = cct0; cct_buf[nb][1] = cct1;
        if (nb == 3 || nb == 7) {                   // renorm row product (8 factors each)
#pragma unroll
            for (int f = 0; f < 4; f++) {
                unsigned pb = __float_as_uint(rpr[f]);
                rea[f] += (int)(pb >> 23) - 127;
                rpr[f] = __uint_as_float((pb & 0x007FFFFFu) | 0x3F800000u);
            }
        }
    }

    // row-side: reduce over lane&3 (same row), write (tj*2 + colhalf) slot
#pragma unroll
    for (int f = 0; f < 4; f++) {
        float se = rse[f];
        float sl = ((float)rea[f] + __log2f(rpr[f])) * 0.69314718055994531f;
        int ct = rct[f];
        se += __shfl_xor_sync(0xffffffffu, se, 1);
        sl += __shfl_xor_sync(0xffffffffu, sl, 1);
        ct += __shfl_xor_sync(0xffffffffu, ct, 1);
        se += __shfl_xor_sync(0xffffffffu, se, 2);
        sl += __shfl_xor_sync(0xffffffffu, sl, 2);
        ct += __shfl_xor_sync(0xffffffffu, ct, 2);
        if ((lane & 3) == 0) {
            int slot = (tj * 2 + (w >> 2)) * N_PTS + grow[f];
            g_pse[slot] = se;
            g_psl[slot] = sl;
            g_pct[slot] = ct;
        }
    }

    // col-side: stage per-thread 32-row partials, fold to (ti*2 + rowhalf) slots
    if (!isdiag) {
        __syncthreads();                            // tiles dead; safe to overwrite
#pragma unroll
        for (int nb = 0; nb < 8; nb++) {
            int c0 = nc + nb * 8 + (lane & 3) * 2;
            st_se[c0 * 32 + cidx] = cse_buf[nb][0];
            st_se[(c0 + 1) * 32 + cidx] = cse_buf[nb][1];
            st_sl[c0 * 32 + cidx] = csl_buf[nb][0];
            st_sl[(c0 + 1) * 32 + cidx] = csl_buf[nb][1];
            st_ct[c0 * 32 + cidx] = cct_buf[nb][0];
            st_ct[(c0 + 1) * 32 + cidx] = cct_buf[nb][1];
        }
        __syncthreads();
        int col = tid >> 1, half = tid & 1;         // 256 threads -> 128 cols x 2 halves
        float se = 0.f, sl = 0.f;
        int ct = 0;
#pragma unroll
        for (int k = 0; k < 16; k++) {
            int o = col * 32 + half * 16 + k;
            se += st_se[o];
            sl += st_sl[o];
            ct += st_ct[o];
        }
        int slot = (ti * 2 + half) * N_PTS + (j0 + col);
        g_pse[slot] = se;
        g_psl[slot] = sl * 0.69314718055994531f;
        g_pct[slot] = ct;
    }
}

__global__ void rowred_kernel() {
    int i = blockIdx.x * blockDim.x + threadIdx.x;
    if (i >= N_PTS) return;
    float se = 0.f, sl = 0.f;
    int ct = 0;
#pragma unroll 8
    for (int t = 0; t < 2 * NT; t++) {
        se += g_pse[t * N_PTS + i];
        sl += g_psl[t * N_PTS + i];
        ct += g_pct[t * N_PTS + i];
    }
    float logA = __logf(fmaxf(se, 1e-30f));
    float P = (float)(ct > 0 ? ct : 1);
    g_rowloss[i] = logA - sl / P;
}

__global__ void final_kernel(float* __restrict__ out) {
    __shared__ float red[256];
    int t = threadIdx.x;
    float acc = 0.f;
#pragma unroll
    for (int it = 0; it < N_PTS / 256; it++)
        acc += g_rowloss[t + it * 256];
    red[t] = acc;
    __syncthreads();
    for (int s = 128; s > 0; s >>= 1) {
        if (t < s) red[t] += red[t + s];
        __syncthreads();
    }
    if (t == 0) out[0] = red[0];
}

extern "C" void kernel_launch(void* const* d_in, const int* in_sizes, int n_in,
                              void* d_out, int out_size) {
    const float* pts = (const float*)d_in[0];
    const long long* labs = (const long long*)d_in[1];
    cudaFuncSetAttribute(main_kernel, cudaFuncAttributeMaxDynamicSharedMemorySize,
                         4 * TILE_B + 256);
    prep_kernel<<<N_PTS / 256, 256>>>(pts, labs);
    main_kernel<<<NPAIR, NTHREADS, 4 * TILE_B + 256>>>();
    rowred_kernel<<<N_PTS / 256, 256>>>();
    final_kernel<<<1, 256>>>((float*)d_out);
}

// round 7
// speedup vs baseline: 1.3861x; 1.2062x over previous
#include <cuda_runtime.h>
#include <cuda_bf16.h>
#include <cstdint>

#define N_PTS 8192
#define DIM 64
#define BM 128
#define NT (N_PTS / BM)            // 64 tiles per side
#define NPAIR (NT * (NT + 1) / 2)  // 2080 tile pairs
#define NTHREADS 512
#define TILE_B 16384               // 128 rows x 64 bf16 (128B rows)
#define NQ 4                       // partial quarters per tile pair side

// ---- scratch (device globals; all writes idempotent, replay-safe) ----
__device__ __align__(16) __nv_bfloat16 g_xhi[N_PTS * DIM];
__device__ __align__(16) __nv_bfloat16 g_xlo[N_PTS * DIM];
__device__ float g_sq[N_PTS];
__device__ float g_ru[N_PTS];
__device__ int   g_lab[N_PTS];
__device__ float g_pse[NQ * NT * N_PTS];
__device__ float g_psl[NQ * NT * N_PTS];
__device__ int   g_pct[NQ * NT * N_PTS];
__device__ float g_rowloss[N_PTS];

__device__ __forceinline__ uint32_t smem_u32(const void* p) {
    uint32_t a;
    asm("{ .reg .u64 t; cvta.to.shared.u64 t, %1; cvt.u32.u64 %0, t; }" : "=r"(a) : "l"(p));
    return a;
}
__device__ __forceinline__ float fast_sqrt(float x) {
    float r; asm("sqrt.approx.f32 %0, %1;" : "=f"(r) : "f"(x)); return r;
}
__device__ __forceinline__ float fast_rcp(float x) {
    float r; asm("rcp.approx.f32 %0, %1;" : "=f"(r) : "f"(x)); return r;
}
__device__ __forceinline__ void ldsm4(uint32_t* r, uint32_t addr) {
    asm volatile("ldmatrix.sync.aligned.m8n8.x4.shared.b16 {%0,%1,%2,%3}, [%4];"
                 : "=r"(r[0]), "=r"(r[1]), "=r"(r[2]), "=r"(r[3]) : "r"(addr));
}
__device__ __forceinline__ void mma_bf16(float* d, const uint32_t* a,
                                         uint32_t b0, uint32_t b1) {
    asm("mma.sync.aligned.m16n8k16.row.col.f32.bf16.bf16.f32 "
        "{%0,%1,%2,%3}, {%4,%5,%6,%7}, {%8,%9}, {%0,%1,%2,%3};"
        : "+f"(d[0]), "+f"(d[1]), "+f"(d[2]), "+f"(d[3])
        : "r"(a[0]), "r"(a[1]), "r"(a[2]), "r"(a[3]), "r"(b0), "r"(b1));
}

// ---- prep: bf16 2-term split + per-point metadata ----
__global__ void prep_kernel(const float* __restrict__ pts,
                            const long long* __restrict__ labs) {
    int i = blockIdx.x * blockDim.x + threadIdx.x;
    if (i >= N_PTS) return;
    float s = 0.f;
#pragma unroll
    for (int q = 0; q < DIM; q++) {
        float x = pts[i * DIM + q];
        s = fmaf(x, x, s);
        __nv_bfloat16 hi = __float2bfloat16(x);
        __nv_bfloat16 lo = __float2bfloat16(x - __bfloat162float(hi));
        g_xhi[i * DIM + q] = hi;
        g_xlo[i * DIM + q] = lo;
    }
    g_sq[i] = s;
    g_ru[i] = 1.0f / (1.0f - s);
    g_lab[i] = (int)labs[i];
}

// ---- main: HMMA tile-pair kernel, 16 warps in 4x4 grid ----
__global__ __launch_bounds__(NTHREADS, 1)
void main_kernel() {
    extern __shared__ __align__(16) char dsm_raw[];
    __shared__ float2 s_mi[BM], s_mj[BM];
    __shared__ int s_li[BM], s_lj[BM];

    uint32_t dsm0 = smem_u32(dsm_raw);
    uint32_t dsm = (dsm0 + 127u) & ~127u;
    char* dsmp = dsm_raw + (dsm - dsm0);

    int tid = threadIdx.x;
    int w = tid >> 5, lane = tid & 31;
    int wr = w & 3, wc = w >> 2;
    int mr = wr * 32, nc = wc * 32;
    int t8 = lane >> 3, rs = lane & 7;

    // decode linear block -> upper-triangular pair (ti <= tj)
    int b = blockIdx.x;
    int ti = (int)floorf((129.0f - sqrtf(16641.0f - 8.0f * (float)b)) * 0.5f);
    if (ti < 0) ti = 0;
    if (ti > NT - 1) ti = NT - 1;
    while (ti > 0 && b < ti * (129 - ti) / 2) ti--;
    while (b >= (ti + 1) * (128 - ti) / 2) ti++;
    int tj = ti + (b - ti * (129 - ti) / 2);
    bool isdiag = (ti == tj);
    int i0 = ti * BM, j0 = tj * BM;

    // ---- load 4 tiles (Ahi,Alo,Bhi,Blo) with XOR-chunk swizzle ----
    const uint4* HI = (const uint4*)g_xhi;
    const uint4* LO = (const uint4*)g_xlo;
#pragma unroll
    for (int it = 0; it < 8; it++) {
        int idx = tid + it * NTHREADS;              // 0..4095
        int tile = idx >> 10;
        int cidx = idx & 1023;
        int row = cidx >> 3, q = cidx & 7;
        int base = (tile & 2) ? j0 : i0;
        const uint4* src = (tile & 1) ? LO : HI;
        uint4 v = src[(base + row) * 8 + q];
        uint32_t off = (uint32_t)(row * 128) + (uint32_t)((q ^ (row & 7)) << 4);
        *(uint4*)(dsmp + tile * TILE_B + off) = v;
    }
    if (tid < BM) {
        int g = j0 + tid;
        s_mj[tid] = make_float2(g_sq[g], g_ru[g]);
        s_lj[tid] = g_lab[g];
    } else if (tid < 2 * BM) {
        int r = tid - BM, g = i0 + r;
        s_mi[r] = make_float2(g_sq[g], g_ru[g]);
        s_li[r] = g_lab[g];
    }
    __syncthreads();

    // ---- 3-term split GEMM via HMMA (per warp: 32 rows x 32 cols) ----
    float d[2][4][4];
#pragma unroll
    for (int mf = 0; mf < 2; mf++)
#pragma unroll
        for (int nb = 0; nb < 4; nb++)
#pragma unroll
            for (int k = 0; k < 4; k++) d[mf][nb][k] = 0.f;

#pragma unroll
    for (int ks = 0; ks < 4; ks++) {
        uint32_t ah[2][4], al[2][4];
#pragma unroll
        for (int mf = 0; mf < 2; mf++) {
            int rowA = mr + mf * 16 + (t8 & 1) * 8 + rs;
            int ch = ks * 2 + (t8 >> 1);
            uint32_t sw = (uint32_t)(rowA * 128) + (uint32_t)((ch ^ (rowA & 7)) << 4);
            ldsm4(ah[mf], dsm + 0 * TILE_B + sw);
            ldsm4(al[mf], dsm + 1 * TILE_B + sw);
        }
#pragma unroll
        for (int nbp = 0; nbp < 2; nbp++) {
            int rowB = nc + nbp * 16 + (t8 >> 1) * 8 + rs;
            int ch = ks * 2 + (t8 & 1);
            uint32_t sw = (uint32_t)(rowB * 128) + (uint32_t)((ch ^ (rowB & 7)) << 4);
            uint32_t bh[4], bl[4];
            ldsm4(bh, dsm + 2 * TILE_B + sw);
            ldsm4(bl, dsm + 3 * TILE_B + sw);
#pragma unroll
            for (int mf = 0; mf < 2; mf++)
#pragma unroll
                for (int nbi = 0; nbi < 2; nbi++) {
                    float* dd = d[mf][nbp * 2 + nbi];
                    mma_bf16(dd, ah[mf], bh[2 * nbi], bh[2 * nbi + 1]);
                    mma_bf16(dd, ah[mf], bl[2 * nbi], bl[2 * nbi + 1]);
                    mma_bf16(dd, al[mf], bh[2 * nbi], bh[2 * nbi + 1]);
                }
        }
    }

    // ---- epilogue: rv = exp(-d) = 1/(z+sqrt(z^2-1)); dual-side accumulate ----
    float sqr[4], rur[4];
    int labr[4], grow[4];
#pragma unroll
    for (int f = 0; f < 4; f++) {                   // f = mf*2 + khalf
        int rloc = mr + (f >> 1) * 16 + (f & 1) * 8 + (lane >> 2);
        grow[f] = i0 + rloc;
        float2 m = s_mi[rloc];
        sqr[f] = m.x; rur[f] = 2.0f * m.y; labr[f] = s_li[rloc];
    }
    float rse[4], rpr[4];
    int rct[4];
#pragma unroll
    for (int f = 0; f < 4; f++) { rse[f] = 0.f; rpr[f] = 1.f; rct[f] = 0; }
    float cse[8], cpr[8];
    int cct[8];
#pragma unroll
    for (int c = 0; c < 8; c++) { cse[c] = 0.f; cpr[c] = 1.f; cct[c] = 0; }

#pragma unroll
    for (int nb = 0; nb < 4; nb++) {
#pragma unroll
        for (int ki = 0; ki < 2; ki++) {            // k&1: which col in pair
            int cloc = nc + nb * 8 + (lane & 3) * 2 + ki;
            int gc = j0 + cloc;
            float2 mj = s_mj[cloc];
            int lj = s_lj[cloc];
            int cc = nb * 2 + ki;
#pragma unroll
            for (int f = 0; f < 4; f++) {           // mf*2 + khalf
                float dot = d[f >> 1][nb][(f & 1) * 2 + ki];
                float sqd = fmaxf(fmaf(-2.0f, dot, sqr[f] + mj.x), 0.f);
                float z = fmaf(sqd * rur[f], mj.y, 1.0f);
                z = fmaxf(z, 1.0f + 1e-7f);
                float s = fast_sqrt(fmaf(z, z, -1.0f));
                float rv = fast_rcp(z + s);
                bool offd = (grow[f] != gc);
                bool pos = offd && (labr[f] == lj);
                float rve = offd ? rv : 0.f;
                float rvp = pos ? rv : 1.f;
                rse[f] += rve; rpr[f] *= rvp; rct[f] += pos;
                cse[cc] += rve; cpr[cc] *= rvp; cct[cc] += pos;
            }
        }
    }

    // row-side: reduce over lane&3 (8 factors each, min ~6e-21: no renorm needed)
#pragma unroll
    for (int f = 0; f < 4; f++) {
        float se = rse[f];
        float sl = __log2f(rpr[f]);
        int ct = rct[f];
        se += __shfl_xor_sync(0xffffffffu, se, 1);
        sl += __shfl_xor_sync(0xffffffffu, sl, 1);
        ct += __shfl_xor_sync(0xffffffffu, ct, 1);
        se += __shfl_xor_sync(0xffffffffu, se, 2);
        sl += __shfl_xor_sync(0xffffffffu, sl, 2);
        ct += __shfl_xor_sync(0xffffffffu, ct, 2);
        if ((lane & 3) == 0) {
            int slot = (tj * NQ + wc) * N_PTS + grow[f];
            g_pse[slot] = se;
            g_psl[slot] = sl * 0.69314718055994531f;
            g_pct[slot] = ct;
        }
    }

    // col-side: reduce over lane>>2 (4 factors each), lanes 0-3 write direct
    if (!isdiag) {
#pragma unroll
        for (int cc = 0; cc < 8; cc++) {
            float se = cse[cc];
            float sl = __log2f(cpr[cc]);
            int ct = cct[cc];
            se += __shfl_xor_sync(0xffffffffu, se, 4);
            sl += __shfl_xor_sync(0xffffffffu, sl, 4);
            ct += __shfl_xor_sync(0xffffffffu, ct, 4);
            se += __shfl_xor_sync(0xffffffffu, se, 8);
            sl += __shfl_xor_sync(0xffffffffu, sl, 8);
            ct += __shfl_xor_sync(0xffffffffu, ct, 8);
            se += __shfl_xor_sync(0xffffffffu, se, 16);
            sl += __shfl_xor_sync(0xffffffffu, sl, 16);
            ct += __shfl_xor_sync(0xffffffffu, ct, 16);
            if (lane < 4) {
                int cloc = nc + (cc >> 1) * 8 + lane * 2 + (cc & 1);
                int slot = (ti * NQ + wr) * N_PTS + (j0 + cloc);
                g_pse[slot] = se;
                g_psl[slot] = sl * 0.69314718055994531f;
                g_pct[slot] = ct;
            }
        }
    }
}

__global__ void rowred_kernel() {
    int i = blockIdx.x * blockDim.x + threadIdx.x;
    if (i >= N_PTS) return;
    float se = 0.f, sl = 0.f;
    int ct = 0;
#pragma unroll 8
    for (int t = 0; t < NQ * NT; t++) {
        se += g_pse[t * N_PTS + i];
        sl += g_psl[t * N_PTS + i];
        ct += g_pct[t * N_PTS + i];
    }
    float logA = __logf(fmaxf(se, 1e-30f));
    float P = (float)(ct > 0 ? ct : 1);
    g_rowloss[i] = logA - sl / P;
}

__global__ void final_kernel(float* __restrict__ out) {
    __shared__ float red[256];
    int t = threadIdx.x;
    float acc = 0.f;
#pragma unroll
    for (int it = 0; it < N_PTS / 256; it++)
        acc += g_rowloss[t + it * 256];
    red[t] = acc;
    __syncthreads();
    for (int s = 128; s > 0; s >>= 1) {
        if (t < s) red[t] += red[t + s];
        __syncthreads();
    }
    if (t == 0) out[0] = red[0];
}

extern "C" void kernel_launch(void* const* d_in, const int* in_sizes, int n_in,
                              void* d_out, int out_size) {
    const float* pts = (const float*)d_in[0];
    const long long* labs = (const long long*)d_in[1];
    cudaFuncSetAttribute(main_kernel, cudaFuncAttributeMaxDynamicSharedMemorySize,
                         4 * TILE_B + 256);
    prep_kernel<<<N_PTS / 256, 256>>>(pts, labs);
    main_kernel<<<NPAIR, NTHREADS, 4 * TILE_B + 256>>>();
    rowred_kernel<<<N_PTS / 256, 256>>>();
    final_kernel<<<1, 256>>>((float*)d_out);
}

// round 8
// speedup vs baseline: 1.5006x; 1.0827x over previous
#include <cuda_runtime.h>
#include <cuda_bf16.h>
#include <cstdint>

#define N_PTS 8192
#define DIM 64
#define BM 128
#define NT (N_PTS / BM)            // 64 tiles per side
#define NPAIR (NT * (NT + 1) / 2)  // 2080 tile pairs
#define NTHREADS 512
#define TILE_B 16384               // 128 rows x 64 bf16 (128B rows)
#define NQ 4                       // partial quarters per tile side
#define GRID 152                   // persistent CTAs (GB300: 152 SMs)
#define BUF_B (4 * TILE_B + 4096)  // 4 tiles + 256 float4 metadata

// ---- scratch (device globals; all writes idempotent, replay-safe) ----
__device__ __align__(16) __nv_bfloat16 g_xhi[N_PTS * DIM];
__device__ __align__(16) __nv_bfloat16 g_xlo[N_PTS * DIM];
__device__ __align__(16) float4 g_meta[N_PTS];   // (sq, ru, lab_bits, 0)
__device__ float g_pse[NQ * NT * N_PTS];
__device__ float g_psl[NQ * NT * N_PTS];
__device__ int   g_pct[NQ * NT * N_PTS];
__device__ float g_rowloss[N_PTS];

__device__ __forceinline__ uint32_t smem_u32(const void* p) {
    uint32_t a;
    asm("{ .reg .u64 t; cvta.to.shared.u64 t, %1; cvt.u32.u64 %0, t; }" : "=r"(a) : "l"(p));
    return a;
}
__device__ __forceinline__ float fast_sqrt(float x) {
    float r; asm("sqrt.approx.f32 %0, %1;" : "=f"(r) : "f"(x)); return r;
}
__device__ __forceinline__ float fast_rcp(float x) {
    float r; asm("rcp.approx.f32 %0, %1;" : "=f"(r) : "f"(x)); return r;
}
__device__ __forceinline__ void ldsm4(uint32_t* r, uint32_t addr) {
    asm volatile("ldmatrix.sync.aligned.m8n8.x4.shared.b16 {%0,%1,%2,%3}, [%4];"
                 : "=r"(r[0]), "=r"(r[1]), "=r"(r[2]), "=r"(r[3]) : "r"(addr));
}
__device__ __forceinline__ void mma_bf16(float* d, const uint32_t* a,
                                         uint32_t b0, uint32_t b1) {
    asm("mma.sync.aligned.m16n8k16.row.col.f32.bf16.bf16.f32 "
        "{%0,%1,%2,%3}, {%4,%5,%6,%7}, {%8,%9}, {%0,%1,%2,%3};"
        : "+f"(d[0]), "+f"(d[1]), "+f"(d[2]), "+f"(d[3])
        : "r"(a[0]), "r"(a[1]), "r"(a[2]), "r"(a[3]), "r"(b0), "r"(b1));
}
__device__ __forceinline__ void cp16(uint32_t dst, const void* src) {
    asm volatile("cp.async.cg.shared.global [%0], [%1], 16;" :: "r"(dst), "l"(src));
}
#define CP_COMMIT() asm volatile("cp.async.commit_group;" ::: "memory")
#define CP_WAIT1()  asm volatile("cp.async.wait_group 1;" ::: "memory")

__device__ __forceinline__ void decode_pair(int b, int& ti, int& tj) {
    int t = (int)floorf((129.0f - sqrtf(16641.0f - 8.0f * (float)b)) * 0.5f);
    if (t < 0) t = 0;
    if (t > NT - 1) t = NT - 1;
    while (t > 0 && b < t * (129 - t) / 2) t--;
    while (b >= (t + 1) * (128 - t) / 2) t++;
    ti = t;
    tj = t + (b - t * (129 - t) / 2);
}

// ---- prep ----
__global__ void prep_kernel(const float* __restrict__ pts,
                            const long long* __restrict__ labs) {
    int i = blockIdx.x * blockDim.x + threadIdx.x;
    if (i >= N_PTS) return;
    float s = 0.f;
#pragma unroll
    for (int q = 0; q < DIM; q++) {
        float x = pts[i * DIM + q];
        s = fmaf(x, x, s);
        __nv_bfloat16 hi = __float2bfloat16(x);
        __nv_bfloat16 lo = __float2bfloat16(x - __bfloat162float(hi));
        g_xhi[i * DIM + q] = hi;
        g_xlo[i * DIM + q] = lo;
    }
    float4 m;
    m.x = s;
    m.y = 1.0f / (1.0f - s);
    m.z = __int_as_float((int)labs[i]);
    m.w = 0.f;
    g_meta[i] = m;
}

// ---- async prefetch of one pair's tiles + metadata into a smem buffer ----
__device__ __forceinline__ void prefetch_pair(uint32_t dbuf, int i0, int j0, int tid) {
    const uint4* HI = (const uint4*)g_xhi;
    const uint4* LO = (const uint4*)g_xlo;
#pragma unroll
    for (int it = 0; it < 8; it++) {
        int idx = tid + it * NTHREADS;              // 0..4095
        int tile = idx >> 10;                       // 0:Ah 1:Al 2:Bh 3:Bl
        int cidx = idx & 1023;
        int row = cidx >> 3, q = cidx & 7;
        int base = (tile & 2) ? j0 : i0;
        const uint4* src = (tile & 1) ? LO : HI;
        uint32_t off = (uint32_t)(row * 128) + (uint32_t)((q ^ (row & 7)) << 4);
        cp16(dbuf + tile * TILE_B + off, &src[(base + row) * 8 + q]);
    }
    if (tid < 256) {                                // 0..127: i rows, 128..255: j cols
        int g = ((tid >> 7) ? j0 : i0) + (tid & 127);
        cp16(dbuf + 4 * TILE_B + tid * 16, &g_meta[g]);
    }
}

// ---- one pair: GEMM + dual-side epilogue (DIAG removes offd checks) ----
template <bool DIAG>
__device__ __forceinline__ void compute_pair(uint32_t dbuf, const char* dbufp,
                                             int ti, int tj, int i0, int j0,
                                             int lane, int wr, int wc) {
    int mr = wr * 32, nc = wc * 32;
    int t8 = lane >> 3, rs = lane & 7;

    float d[2][4][4];
#pragma unroll
    for (int mf = 0; mf < 2; mf++)
#pragma unroll
        for (int nb = 0; nb < 4; nb++)
#pragma unroll
            for (int k = 0; k < 4; k++) d[mf][nb][k] = 0.f;

#pragma unroll
    for (int ks = 0; ks < 4; ks++) {
        uint32_t ah[2][4], al[2][4];
#pragma unroll
        for (int mf = 0; mf < 2; mf++) {
            int rowA = mr + mf * 16 + (t8 & 1) * 8 + rs;
            int ch = ks * 2 + (t8 >> 1);
            uint32_t sw = (uint32_t)(rowA * 128) + (uint32_t)((ch ^ (rowA & 7)) << 4);
            ldsm4(ah[mf], dbuf + 0 * TILE_B + sw);
            ldsm4(al[mf], dbuf + 1 * TILE_B + sw);
        }
#pragma unroll
        for (int nbp = 0; nbp < 2; nbp++) {
            int rowB = nc + nbp * 16 + (t8 >> 1) * 8 + rs;
            int ch = ks * 2 + (t8 & 1);
            uint32_t sw = (uint32_t)(rowB * 128) + (uint32_t)((ch ^ (rowB & 7)) << 4);
            uint32_t bh[4], bl[4];
            ldsm4(bh, dbuf + 2 * TILE_B + sw);
            ldsm4(bl, dbuf + 3 * TILE_B + sw);
#pragma unroll
            for (int mf = 0; mf < 2; mf++)
#pragma unroll
                for (int nbi = 0; nbi < 2; nbi++) {
                    float* dd = d[mf][nbp * 2 + nbi];
                    mma_bf16(dd, ah[mf], bh[2 * nbi], bh[2 * nbi + 1]);
                    mma_bf16(dd, ah[mf], bl[2 * nbi], bl[2 * nbi + 1]);
                    mma_bf16(dd, al[mf], bh[2 * nbi], bh[2 * nbi + 1]);
                }
        }
    }

    const float4* meta_i = (const float4*)(dbufp + 4 * TILE_B);
    const float4* meta_j = meta_i + 128;

    float sqr[4], rur[4];
    int labr[4], rloc4[4];
#pragma unroll
    for (int f = 0; f < 4; f++) {
        int rloc = mr + (f >> 1) * 16 + (f & 1) * 8 + (lane >> 2);
        rloc4[f] = rloc;
        float4 m = meta_i[rloc];
        sqr[f] = m.x; rur[f] = 2.0f * m.y; labr[f] = __float_as_int(m.z);
    }
    float rse[4], rpr[4];
    int rct[4];
#pragma unroll
    for (int f = 0; f < 4; f++) { rse[f] = 0.f; rpr[f] = 1.f; rct[f] = 0; }
    float cse[8], cpr[8];
    int cct[8];
#pragma unroll
    for (int c = 0; c < 8; c++) { cse[c] = 0.f; cpr[c] = 1.f; cct[c] = 0; }

#pragma unroll
    for (int nb = 0; nb < 4; nb++) {
#pragma unroll
        for (int ki = 0; ki < 2; ki++) {
            int cloc = nc + nb * 8 + (lane & 3) * 2 + ki;
            float4 mj = meta_j[cloc];
            int lj = __float_as_int(mj.z);
            int cc = nb * 2 + ki;
#pragma unroll
            for (int f = 0; f < 4; f++) {
                float dot = d[f >> 1][nb][(f & 1) * 2 + ki];
                float sqd = fmaxf(fmaf(-2.0f, dot, sqr[f] + mj.x), 0.f);
                float z = fmaf(sqd * rur[f], mj.y, 1.0f);
                z = fmaxf(z, 1.0f + 1e-7f);
                float s = fast_sqrt(fmaf(z, z, -1.0f));
                float rv = fast_rcp(z + s);
                bool pos;
                float rve;
                if (DIAG) {
                    bool offd = (rloc4[f] != cloc);
                    pos = offd && (labr[f] == lj);
                    rve = offd ? rv : 0.f;
                } else {
                    pos = (labr[f] == lj);
                    rve = rv;
                }
                float rvp = pos ? rv : 1.f;
                rse[f] += rve; rpr[f] *= rvp; rct[f] += pos;
                cse[cc] += rve; cpr[cc] *= rvp; cct[cc] += pos;
            }
        }
    }

    // row-side: reduce over lane&3; products have <=8 factors (>=6e-21), no renorm
#pragma unroll
    for (int f = 0; f < 4; f++) {
        float se = rse[f];
        float sl = __log2f(rpr[f]);
        int ct = rct[f];
        se += __shfl_xor_sync(0xffffffffu, se, 1);
        sl += __shfl_xor_sync(0xffffffffu, sl, 1);
        ct += __shfl_xor_sync(0xffffffffu, ct, 1);
        se += __shfl_xor_sync(0xffffffffu, se, 2);
        sl += __shfl_xor_sync(0xffffffffu, sl, 2);
        ct += __shfl_xor_sync(0xffffffffu, ct, 2);
        if ((lane & 3) == 0) {
            int slot = (tj * NQ + wc) * N_PTS + (i0 + rloc4[f]);
            g_pse[slot] = se;
            g_psl[slot] = sl * 0.69314718055994531f;
            g_pct[slot] = ct;
        }
    }

    // col-side: reduce over lane>>2; skipped on diagonal pairs
    if (!DIAG) {
#pragma unroll
        for (int cc = 0; cc < 8; cc++) {
            float se = cse[cc];
            float sl = __log2f(cpr[cc]);
            int ct = cct[cc];
            se += __shfl_xor_sync(0xffffffffu, se, 4);
            sl += __shfl_xor_sync(0xffffffffu, sl, 4);
            ct += __shfl_xor_sync(0xffffffffu, ct, 4);
            se += __shfl_xor_sync(0xffffffffu, se, 8);
            sl += __shfl_xor_sync(0xffffffffu, sl, 8);
            ct += __shfl_xor_sync(0xffffffffu, ct, 8);
            se += __shfl_xor_sync(0xffffffffu, se, 16);
            sl += __shfl_xor_sync(0xffffffffu, sl, 16);
            ct += __shfl_xor_sync(0xffffffffu, ct, 16);
            if (lane < 4) {
                int cloc = nc + (cc >> 1) * 8 + lane * 2 + (cc & 1);
                int slot = (ti * NQ + wr) * N_PTS + (j0 + cloc);
                g_pse[slot] = se;
                g_psl[slot] = sl * 0.69314718055994531f;
                g_pct[slot] = ct;
            }
        }
    }
}

// ---- main: persistent double-buffered HMMA pipeline ----
__global__ __launch_bounds__(NTHREADS, 1)
void main_kernel() {
    extern __shared__ __align__(16) char dsm_raw[];
    uint32_t dsm0 = smem_u32(dsm_raw);
    uint32_t dsm = (dsm0 + 127u) & ~127u;
    char* dsmp = dsm_raw + (dsm - dsm0);

    int tid = threadIdx.x;
    int w = tid >> 5, lane = tid & 31;
    int wr = w & 3, wc = w >> 2;

    int p = blockIdx.x;
    if (p < NPAIR) {
        int ti, tj;
        decode_pair(p, ti, tj);
        prefetch_pair(dsm, ti * BM, tj * BM, tid);
    }
    CP_COMMIT();

    int it = 0;
    for (; p < NPAIR; p += GRID, it++) {
        uint32_t dbuf = dsm + (uint32_t)(it & 1) * BUF_B;
        const char* dbufp = dsmp + (it & 1) * BUF_B;

        int pn = p + GRID;
        if (pn < NPAIR) {
            int tin, tjn;
            decode_pair(pn, tin, tjn);
            prefetch_pair(dsm + (uint32_t)((it + 1) & 1) * BUF_B,
                          tin * BM, tjn * BM, tid);
        }
        CP_COMMIT();
        CP_WAIT1();
        __syncthreads();

        int ti, tj;
        decode_pair(p, ti, tj);
        if (ti == tj)
            compute_pair<true>(dbuf, dbufp, ti, tj, ti * BM, tj * BM, lane, wr, wc);
        else
            compute_pair<false>(dbuf, dbufp, ti, tj, ti * BM, tj * BM, lane, wr, wc);
        __syncthreads();
    }
}

__global__ void rowred_kernel() {
    int i = blockIdx.x * blockDim.x + threadIdx.x;
    if (i >= N_PTS) return;
    float se = 0.f, sl = 0.f;
    int ct = 0;
#pragma unroll 8
    for (int t = 0; t < NQ * NT; t++) {
        se += g_pse[t * N_PTS + i];
        sl += g_psl[t * N_PTS + i];
        ct += g_pct[t * N_PTS + i];
    }
    float logA = __logf(fmaxf(se, 1e-30f));
    float P = (float)(ct > 0 ? ct : 1);
    g_rowloss[i] = logA - sl / P;
}

__global__ void final_kernel(float* __restrict__ out) {
    __shared__ float red[256];
    int t = threadIdx.x;
    float acc = 0.f;
#pragma unroll
    for (int it = 0; it < N_PTS / 256; it++)
        acc += g_rowloss[t + it * 256];
    red[t] = acc;
    __syncthreads();
    for (int s = 128; s > 0; s >>= 1) {
        if (t < s) red[t] += red[t + s];
        __syncthreads();
    }
    if (t == 0) out[0] = red[0];
}

extern "C" void kernel_launch(void* const* d_in, const int* in_sizes, int n_in,
                              void* d_out, int out_size) {
    const float* pts = (const float*)d_in[0];
    const long long* labs = (const long long*)d_in[1];
    cudaFuncSetAttribute(main_kernel, cudaFuncAttributeMaxDynamicSharedMemorySize,
                         2 * BUF_B + 128);
    prep_kernel<<<N_PTS / 256, 256>>>(pts, labs);
    main_kernel<<<GRID, NTHREADS, 2 * BUF_B + 128>>>();
    rowred_kernel<<<N_PTS / 256, 256>>>();
    final_kernel<<<1, 256>>>((float*)d_out);
}

// round 9
// speedup vs baseline: 1.5908x; 1.0601x over previous
#include <cuda_runtime.h>
#include <cuda_bf16.h>
#include <cstdint>

#define N_PTS 8192
#define DIM 64
#define BM 128
#define NT (N_PTS / BM)            // 64 tiles per side
#define NPAIR (NT * (NT + 1) / 2)  // 2080 tile pairs
#define NTHREADS 512
#define TILE_B 16384               // 128 rows x 64 bf16 (128B rows)
#define NQ 4                       // partial quarters per tile side
#define GRID 152                   // persistent CTAs
#define BUF_B (4 * TILE_B + 4096)  // 4 tiles + 256 float4 metadata

// ---- scratch (device globals; all writes idempotent, replay-safe) ----
__device__ __align__(16) __nv_bfloat16 g_xhi[N_PTS * DIM];
__device__ __align__(16) __nv_bfloat16 g_xlo[N_PTS * DIM];
__device__ __align__(16) float4 g_meta[N_PTS];   // (sq, ru, lab_bits, 0)
__device__ float g_pse[NQ * NT * N_PTS];
__device__ float g_psl[NQ * NT * N_PTS];
__device__ int   g_pct[NQ * NT * N_PTS];
__device__ float g_rowloss[N_PTS];

__device__ __forceinline__ uint32_t smem_u32(const void* p) {
    uint32_t a;
    asm("{ .reg .u64 t; cvta.to.shared.u64 t, %1; cvt.u32.u64 %0, t; }" : "=r"(a) : "l"(p));
    return a;
}
__device__ __forceinline__ float fast_sqrt(float x) {
    float r; asm("sqrt.approx.f32 %0, %1;" : "=f"(r) : "f"(x)); return r;
}
__device__ __forceinline__ float fast_rcp(float x) {
    float r; asm("rcp.approx.f32 %0, %1;" : "=f"(r) : "f"(x)); return r;
}
__device__ __forceinline__ void ldsm4(uint32_t* r, uint32_t addr) {
    asm volatile("ldmatrix.sync.aligned.m8n8.x4.shared.b16 {%0,%1,%2,%3}, [%4];"
                 : "=r"(r[0]), "=r"(r[1]), "=r"(r[2]), "=r"(r[3]) : "r"(addr));
}
__device__ __forceinline__ void mma_bf16(float* d, const uint32_t* a,
                                         uint32_t b0, uint32_t b1) {
    asm("mma.sync.aligned.m16n8k16.row.col.f32.bf16.bf16.f32 "
        "{%0,%1,%2,%3}, {%4,%5,%6,%7}, {%8,%9}, {%0,%1,%2,%3};"
        : "+f"(d[0]), "+f"(d[1]), "+f"(d[2]), "+f"(d[3])
        : "r"(a[0]), "r"(a[1]), "r"(a[2]), "r"(a[3]), "r"(b0), "r"(b1));
}
__device__ __forceinline__ void cp16(uint32_t dst, const void* src) {
    asm volatile("cp.async.cg.shared.global [%0], [%1], 16;" :: "r"(dst), "l"(src));
}
#define CP_COMMIT() asm volatile("cp.async.commit_group;" ::: "memory")
#define CP_WAIT1()  asm volatile("cp.async.wait_group 1;" ::: "memory")

__device__ __forceinline__ void decode_pair(int b, int& ti, int& tj) {
    int t = (int)floorf((129.0f - sqrtf(16641.0f - 8.0f * (float)b)) * 0.5f);
    if (t < 0) t = 0;
    if (t > NT - 1) t = NT - 1;
    while (t > 0 && b < t * (129 - t) / 2) t--;
    while (b >= (t + 1) * (128 - t) / 2) t++;
    ti = t;
    tj = t + (b - t * (129 - t) / 2);
}

// ---- prep ----
__global__ void prep_kernel(const float* __restrict__ pts,
                            const long long* __restrict__ labs) {
    int i = blockIdx.x * blockDim.x + threadIdx.x;
    if (i >= N_PTS) return;
    float s = 0.f;
#pragma unroll
    for (int q = 0; q < DIM; q++) {
        float x = pts[i * DIM + q];
        s = fmaf(x, x, s);
        __nv_bfloat16 hi = __float2bfloat16(x);
        __nv_bfloat16 lo = __float2bfloat16(x - __bfloat162float(hi));
        g_xhi[i * DIM + q] = hi;
        g_xlo[i * DIM + q] = lo;
    }
    float4 m;
    m.x = s;
    m.y = 1.0f / (1.0f - s);
    m.z = __int_as_float((int)labs[i]);
    m.w = 0.f;
    g_meta[i] = m;
}

// ---- async prefetch of one pair's tiles + metadata into a smem buffer ----
__device__ __forceinline__ void prefetch_pair(uint32_t dbuf, int i0, int j0, int tid) {
    const uint4* HI = (const uint4*)g_xhi;
    const uint4* LO = (const uint4*)g_xlo;
#pragma unroll
    for (int it = 0; it < 8; it++) {
        int idx = tid + it * NTHREADS;              // 0..4095
        int tile = idx >> 10;                       // 0:Ah 1:Al 2:Bh 3:Bl
        int cidx = idx & 1023;
        int row = cidx >> 3, q = cidx & 7;
        int base = (tile & 2) ? j0 : i0;
        const uint4* src = (tile & 1) ? LO : HI;
        uint32_t off = (uint32_t)(row * 128) + (uint32_t)((q ^ (row & 7)) << 4);
        cp16(dbuf + tile * TILE_B + off, &src[(base + row) * 8 + q]);
    }
    if (tid < 256) {                                // 0..127: i rows, 128..255: j cols
        int g = ((tid >> 7) ? j0 : i0) + (tid & 127);
        cp16(dbuf + 4 * TILE_B + tid * 16, &g_meta[g]);
    }
}

// ---- one pair: GEMM (term-major, chain-free) + dual-side epilogue ----
template <bool DIAG>
__device__ __forceinline__ void compute_pair(uint32_t dbuf, const char* dbufp,
                                             int ti, int tj, int i0, int j0,
                                             int lane, int wr, int wc) {
    int mr = wr * 32, nc = wc * 32;
    int t8 = lane >> 3, rs = lane & 7;

    float d[2][4][4];
#pragma unroll
    for (int mf = 0; mf < 2; mf++)
#pragma unroll
        for (int nb = 0; nb < 4; nb++)
#pragma unroll
            for (int k = 0; k < 4; k++) d[mf][nb][k] = 0.f;

#pragma unroll
    for (int ks = 0; ks < 4; ks++) {
        uint32_t ah[2][4], al[2][4], bh[2][4], bl[2][4];
#pragma unroll
        for (int mf = 0; mf < 2; mf++) {
            int rowA = mr + mf * 16 + (t8 & 1) * 8 + rs;
            int ch = ks * 2 + (t8 >> 1);
            uint32_t sw = (uint32_t)(rowA * 128) + (uint32_t)((ch ^ (rowA & 7)) << 4);
            ldsm4(ah[mf], dbuf + 0 * TILE_B + sw);
            ldsm4(al[mf], dbuf + 1 * TILE_B + sw);
        }
#pragma unroll
        for (int nbp = 0; nbp < 2; nbp++) {
            int rowB = nc + nbp * 16 + (t8 >> 1) * 8 + rs;
            int ch = ks * 2 + (t8 & 1);
            uint32_t sw = (uint32_t)(rowB * 128) + (uint32_t)((ch ^ (rowB & 7)) << 4);
            ldsm4(bh[nbp], dbuf + 2 * TILE_B + sw);
            ldsm4(bl[nbp], dbuf + 3 * TILE_B + sw);
        }
        // term-major issue: 8 distinct accumulators between any dd reuse
#pragma unroll
        for (int mf = 0; mf < 2; mf++)
#pragma unroll
            for (int nbp = 0; nbp < 2; nbp++)
#pragma unroll
                for (int nbi = 0; nbi < 2; nbi++)
                    mma_bf16(d[mf][nbp * 2 + nbi], ah[mf],
                             bh[nbp][2 * nbi], bh[nbp][2 * nbi + 1]);
#pragma unroll
        for (int mf = 0; mf < 2; mf++)
#pragma unroll
            for (int nbp = 0; nbp < 2; nbp++)
#pragma unroll
                for (int nbi = 0; nbi < 2; nbi++)
                    mma_bf16(d[mf][nbp * 2 + nbi], ah[mf],
                             bl[nbp][2 * nbi], bl[nbp][2 * nbi + 1]);
#pragma unroll
        for (int mf = 0; mf < 2; mf++)
#pragma unroll
            for (int nbp = 0; nbp < 2; nbp++)
#pragma unroll
                for (int nbi = 0; nbi < 2; nbi++)
                    mma_bf16(d[mf][nbp * 2 + nbi], al[mf],
                             bh[nbp][2 * nbi], bh[nbp][2 * nbi + 1]);
    }

    const float4* meta_i = (const float4*)(dbufp + 4 * TILE_B);
    const float4* meta_j = meta_i + 128;

    float sqr[4], rur[4];
    int labr[4], rloc4[4];
#pragma unroll
    for (int f = 0; f < 4; f++) {
        int rloc = mr + (f >> 1) * 16 + (f & 1) * 8 + (lane >> 2);
        rloc4[f] = rloc;
        float4 m = meta_i[rloc];
        sqr[f] = m.x; rur[f] = 2.0f * m.y; labr[f] = __float_as_int(m.z);
    }
    float rse[4], rpr[4];
    int rct[4];
#pragma unroll
    for (int f = 0; f < 4; f++) { rse[f] = 0.f; rpr[f] = 1.f; rct[f] = 0; }

#pragma unroll
    for (int nb = 0; nb < 4; nb++) {
#pragma unroll
        for (int ki = 0; ki < 2; ki++) {
            int cloc = nc + nb * 8 + (lane & 3) * 2 + ki;
            float4 mj = meta_j[cloc];
            int lj = __float_as_int(mj.z);
            float cse = 0.f, cpr = 1.f;
            int cct = 0;
#pragma unroll
            for (int f = 0; f < 4; f++) {
                float dot = d[f >> 1][nb][(f & 1) * 2 + ki];
                float sqd = fmaxf(fmaf(-2.0f, dot, sqr[f] + mj.x), 0.f);
                float z = fmaf(sqd * rur[f], mj.y, 1.0f);
                z = fmaxf(z, 1.0f + 1e-7f);
                float s = fast_sqrt(fmaf(z, z, -1.0f));
                float rv = fast_rcp(z + s);
                bool pos;
                float rve;
                if (DIAG) {
                    bool offd = (rloc4[f] != cloc);
                    pos = offd && (labr[f] == lj);
                    rve = offd ? rv : 0.f;
                } else {
                    pos = (labr[f] == lj);
                    rve = rv;
                }
                float rvp = pos ? rv : 1.f;
                rse[f] += rve; rpr[f] *= rvp; rct[f] += pos;
                cse += rve; cpr *= rvp; cct += pos;
            }
            // col-side inline reduce over lane>>2 (skip on diagonal pairs)
            if (!DIAG) {
                float csl = __log2f(cpr);
                cse += __shfl_xor_sync(0xffffffffu, cse, 4);
                csl += __shfl_xor_sync(0xffffffffu, csl, 4);
                cct += __shfl_xor_sync(0xffffffffu, cct, 4);
                cse += __shfl_xor_sync(0xffffffffu, cse, 8);
                csl += __shfl_xor_sync(0xffffffffu, csl, 8);
                cct += __shfl_xor_sync(0xffffffffu, cct, 8);
                cse += __shfl_xor_sync(0xffffffffu, cse, 16);
                csl += __shfl_xor_sync(0xffffffffu, csl, 16);
                cct += __shfl_xor_sync(0xffffffffu, cct, 16);
                if (lane < 4) {
                    int cstore = nc + nb * 8 + lane * 2 + ki;
                    int slot = (ti * NQ + wr) * N_PTS + (j0 + cstore);
                    g_pse[slot] = cse;
                    g_psl[slot] = csl * 0.69314718055994531f;
                    g_pct[slot] = cct;
                }
            }
        }
    }

    // row-side: reduce over lane&3; products have <=8 factors (>=6e-21), no renorm
#pragma unroll
    for (int f = 0; f < 4; f++) {
        float se = rse[f];
        float sl = __log2f(rpr[f]);
        int ct = rct[f];
        se += __shfl_xor_sync(0xffffffffu, se, 1);
        sl += __shfl_xor_sync(0xffffffffu, sl, 1);
        ct += __shfl_xor_sync(0xffffffffu, ct, 1);
        se += __shfl_xor_sync(0xffffffffu, se, 2);
        sl += __shfl_xor_sync(0xffffffffu, sl, 2);
        ct += __shfl_xor_sync(0xffffffffu, ct, 2);
        if ((lane & 3) == 0) {
            int slot = (tj * NQ + wc) * N_PTS + (i0 + rloc4[f]);
            g_pse[slot] = se;
            g_psl[slot] = sl * 0.69314718055994531f;
            g_pct[slot] = ct;
        }
    }
}

// ---- main: persistent double-buffered HMMA pipeline ----
__global__ __launch_bounds__(NTHREADS, 1)
void main_kernel() {
    extern __shared__ __align__(16) char dsm_raw[];
    uint32_t dsm0 = smem_u32(dsm_raw);
    uint32_t dsm = (dsm0 + 127u) & ~127u;
    char* dsmp = dsm_raw + (dsm - dsm0);

    int tid = threadIdx.x;
    int w = tid >> 5, lane = tid & 31;
    int wr = w & 3, wc = w >> 2;

    int p = blockIdx.x;
    int ti = 0, tj = 0;
    if (p < NPAIR) {
        decode_pair(p, ti, tj);
        prefetch_pair(dsm, ti * BM, tj * BM, tid);
    }
    CP_COMMIT();

    int it = 0;
    for (; p < NPAIR; p += GRID, it++) {
        uint32_t dbuf = dsm + (uint32_t)(it & 1) * BUF_B;
        const char* dbufp = dsmp + (it & 1) * BUF_B;

        int tin = 0, tjn = 0;
        int pn = p + GRID;
        bool havenext = (pn < NPAIR);
        if (havenext) {
            decode_pair(pn, tin, tjn);
            prefetch_pair(dsm + (uint32_t)((it + 1) & 1) * BUF_B,
                          tin * BM, tjn * BM, tid);
        }
        CP_COMMIT();
        CP_WAIT1();
        __syncthreads();

        if (ti == tj)
            compute_pair<true>(dbuf, dbufp, ti, tj, ti * BM, tj * BM, lane, wr, wc);
        else
            compute_pair<false>(dbuf, dbufp, ti, tj, ti * BM, tj * BM, lane, wr, wc);
        __syncthreads();

        ti = tin; tj = tjn;
    }
}

__global__ void rowred_kernel() {
    int i = blockIdx.x * blockDim.x + threadIdx.x;
    if (i >= N_PTS) return;
    float se = 0.f, sl = 0.f;
    int ct = 0;
#pragma unroll 8
    for (int t = 0; t < NQ * NT; t++) {
        se += g_pse[t * N_PTS + i];
        sl += g_psl[t * N_PTS + i];
        ct += g_pct[t * N_PTS + i];
    }
    float logA = __logf(fmaxf(se, 1e-30f));
    float P = (float)(ct > 0 ? ct : 1);
    g_rowloss[i] = logA - sl / P;
}

__global__ void final_kernel(float* __restrict__ out) {
    __shared__ float red[256];
    int t = threadIdx.x;
    float acc = 0.f;
#pragma unroll
    for (int it = 0; it < N_PTS / 256; it++)
        acc += g_rowloss[t + it * 256];
    red[t] = acc;
    __syncthreads();
    for (int s = 128; s > 0; s >>= 1) {
        if (t < s) red[t] += red[t + s];
        __syncthreads();
    }
    if (t == 0) out[0] = red[0];
}

extern "C" void kernel_launch(void* const* d_in, const int* in_sizes, int n_in,
                              void* d_out, int out_size) {
    const float* pts = (const float*)d_in[0];
    const long long* labs = (const long long*)d_in[1];
    cudaFuncSetAttribute(main_kernel, cudaFuncAttributeMaxDynamicSharedMemorySize,
                         2 * BUF_B + 128);
    prep_kernel<<<N_PTS / 256, 256>>>(pts, labs);
    main_kernel<<<GRID, NTHREADS, 2 * BUF_B + 128>>>();
    rowred_kernel<<<N_PTS / 256, 256>>>();
    final_kernel<<<1, 256>>>((float*)d_out);
}